// round 8
// baseline (speedup 1.0000x reference)
#include <cuda_runtime.h>
#include <cuda_fp16.h>
#include <math.h>
#include <stdint.h>

#define N_ROWS  131072
#define S_DIM   64
#define H_DIM   128
#define K_CODES 512
#define A_DIM   8
#define TM      128
#define NTHREADS 512
#define MARGIN  0.05f

typedef uint32_t u32;

// ===================== warp-level tensor ops (base PTX) =====================
#define LDSM4(r, addr)                                                        \
    asm volatile("ldmatrix.sync.aligned.m8n8.x4.shared.b16 {%0,%1,%2,%3}, [%4];" \
                 : "=r"((r)[0]), "=r"((r)[1]), "=r"((r)[2]), "=r"((r)[3])     \
                 : "r"(addr))

__device__ __forceinline__ void mma16816(float* c, const u32* a, u32 b0, u32 b1) {
    asm volatile("mma.sync.aligned.m16n8k16.row.col.f32.f16.f16.f32 "
                 "{%0,%1,%2,%3}, {%4,%5,%6,%7}, {%8,%9}, {%0,%1,%2,%3};"
                 : "+f"(c[0]), "+f"(c[1]), "+f"(c[2]), "+f"(c[3])
                 : "r"(a[0]), "r"(a[1]), "r"(a[2]), "r"(a[3]), "r"(b0), "r"(b1));
}

__device__ __forceinline__ u32 smem_u32(const void* p) {
    u32 a; asm("{ .reg .u64 t; cvta.to.shared.u64 t, %1; cvt.u32.u64 %0, t; }"
               : "=r"(a) : "l"(p)); return a;
}
__device__ __forceinline__ u32 pkh(float a, float b) {
    __half2 t; t.x = __float2half_rn(a); t.y = __float2half_rn(b);
    return *reinterpret_cast<u32*>(&t);
}
__device__ __forceinline__ void cpa16(u32 dst, const void* src) {
    asm volatile("cp.async.cg.shared.global [%0], [%1], 16;"
                 :: "r"(dst), "l"(src) : "memory");
}
#define CP_COMMIT() asm volatile("cp.async.commit_group;" ::: "memory")
#define CP_WAIT(n)  asm volatile("cp.async.wait_group %0;" :: "n"(n) : "memory")

// ===================== device globals =====================
__device__ float g_ee[K_CODES];
__device__ float g_probs[K_CODES * A_DIM];
__device__ float g_value[K_CODES];

// fp16 images:  W1T hi/lo, WhT hi/lo, E hi-only (4 tiles x [128][136])
#define IMG_W1 0
#define IMG_WH 18432
#define IMG_E  53248
__device__ __half g_img[122880];

// ===================== kernel 1: merged prelim =====================
__global__ void prep_all(const float* __restrict__ emb,
                         const float* __restrict__ Wa, const float* __restrict__ ba,
                         const float* __restrict__ Wv, const float* __restrict__ bv,
                         const float* __restrict__ W1, const float* __restrict__ Wh)
{
    if (blockIdx.x < 64) {
        int code = blockIdx.x * 8 + (threadIdx.x >> 5);
        int lane = threadIdx.x & 31;
        const float* e = emb + code * H_DIM;
        double ee = 0.0;
        float logit[A_DIM];
#pragma unroll
        for (int a = 0; a < A_DIM; a++) logit[a] = 0.0f;
        float val = 0.0f;
#pragma unroll
        for (int j = 0; j < 4; j++) {
            int d = lane + 32 * j;
            float ej = e[d];
            ee += (double)ej * (double)ej;
#pragma unroll
            for (int a = 0; a < A_DIM; a++) logit[a] = fmaf(ej, Wa[d * A_DIM + a], logit[a]);
            val = fmaf(ej, Wv[d], val);
        }
#pragma unroll
        for (int off = 16; off; off >>= 1) {
            ee  += __shfl_xor_sync(0xFFFFFFFFu, ee,  off);
            val += __shfl_xor_sync(0xFFFFFFFFu, val, off);
#pragma unroll
            for (int a = 0; a < A_DIM; a++)
                logit[a] += __shfl_xor_sync(0xFFFFFFFFu, logit[a], off);
        }
        if (lane == 0) {
#pragma unroll
            for (int a = 0; a < A_DIM; a++) logit[a] += ba[a];
            g_ee[code] = (float)ee;
            g_value[code] = val + bv[0];
            float m = logit[0];
#pragma unroll
            for (int a = 1; a < A_DIM; a++) m = fmaxf(m, logit[a]);
            float p[A_DIM], s = 0.0f;
#pragma unroll
            for (int a = 0; a < A_DIM; a++) { p[a] = expf(logit[a] - m); s += p[a]; }
#pragma unroll
            for (int a = 0; a < A_DIM; a++) g_probs[code * A_DIM + a] = p[a] / s;
        }
        return;
    }
    int idx = (blockIdx.x - 64) * 256 + threadIdx.x;
    if (idx < 8192) {                       // W1T hi/lo
        int n = idx >> 6, s = idx & 63;
        float v = W1[s * H_DIM + n];
        __half h = __float2half_rn(v);
        __half l = __float2half_rn(v - __half2float(h));
        int o = n * 72 + s;
        g_img[IMG_W1 + o] = h;
        g_img[IMG_W1 + 9216 + o] = l;
    } else if (idx < 24576) {               // WhT hi/lo
        int j = idx - 8192;
        int n = j >> 7, k = j & 127;
        float v = Wh[k * H_DIM + n];
        __half h = __float2half_rn(v);
        __half l = __float2half_rn(v - __half2float(h));
        int o = n * 136 + k;
        g_img[IMG_WH + o] = h;
        g_img[IMG_WH + 17408 + o] = l;
    } else if (idx < 90112) {               // E hi only
        int j = idx - 24576;
        int g = j >> 7, d = j & 127;
        int t = g >> 7, c = g & 127;
        g_img[IMG_E + t * 17408 + c * 136 + d] = __float2half_rn(emb[g * H_DIM + d]);
    }
}

// ===================== kernel 2: fused main =====================
#define OFF_B1   0        // float[128]
#define OFF_BH   512
#define OFF_VV   1024     // float[128][4]
#define OFF_EE   3072     // float[512]
#define OFF_CD   5120     // float[128][12]
#define OFF_CI   11264    // int[128][12]
#define REG_A    17408    // input hi|lo(+18432) p144; W1 hi(+36864)|lo(+55296); later x2 hi|lo(+34816) p272
#define REG_C    91136    // x1 hi|lo(+34816) p272; later E tiles 0,1
#define REG_D    160768   // Wh hi|lo(+34816) p272; later E tiles 2,3
#define SMEM_BYTES 230400

// 3-pass split GEMM (encoder), warp tile 32x32, pass-major
template<int KS>
__device__ __forceinline__ void run_gemm(u32 aH, u32 aL, u32 bH, u32 bL,
                                         int pitchA, int pitchB,
                                         int lane, int wrow, int cbase, float (*acc)[4])
{
    const u32 aoff0 = (u32)(wrow + (lane & 15)) * pitchA + (u32)(lane >> 4) * 16;
    const u32 aoff1 = aoff0 + 16u * pitchA;
    const u32 boff = (u32)(cbase + (lane & 7) + ((lane >> 4) << 3)) * pitchB
                   + (u32)((lane >> 3) & 1) * 16;
#pragma unroll
    for (int ks = 0; ks < KS; ks++) {
        u32 ah0[4], al0[4], ah1[4], al1[4];
        u32 bh0[4], bh1[4], bl0[4], bl1[4];
        LDSM4(ah0, aH + aoff0 + ks * 32);
        LDSM4(ah1, aH + aoff1 + ks * 32);
        LDSM4(bh0, bH + boff + ks * 32);
        LDSM4(bh1, bH + boff + 16u * pitchB + ks * 32);
        LDSM4(al0, aL + aoff0 + ks * 32);
        LDSM4(al1, aL + aoff1 + ks * 32);
        LDSM4(bl0, bL + boff + ks * 32);
        LDSM4(bl1, bL + boff + 16u * pitchB + ks * 32);
        mma16816(acc[0], ah0, bh0[0], bh0[1]);
        mma16816(acc[1], ah0, bh0[2], bh0[3]);
        mma16816(acc[2], ah0, bh1[0], bh1[1]);
        mma16816(acc[3], ah0, bh1[2], bh1[3]);
        mma16816(acc[4], ah1, bh0[0], bh0[1]);
        mma16816(acc[5], ah1, bh0[2], bh0[3]);
        mma16816(acc[6], ah1, bh1[0], bh1[1]);
        mma16816(acc[7], ah1, bh1[2], bh1[3]);
        mma16816(acc[0], al0, bh0[0], bh0[1]);
        mma16816(acc[1], al0, bh0[2], bh0[3]);
        mma16816(acc[2], al0, bh1[0], bh1[1]);
        mma16816(acc[3], al0, bh1[2], bh1[3]);
        mma16816(acc[4], al1, bh0[0], bh0[1]);
        mma16816(acc[5], al1, bh0[2], bh0[3]);
        mma16816(acc[6], al1, bh1[0], bh1[1]);
        mma16816(acc[7], al1, bh1[2], bh1[3]);
        mma16816(acc[0], ah0, bl0[0], bl0[1]);
        mma16816(acc[1], ah0, bl0[2], bl0[3]);
        mma16816(acc[2], ah0, bl1[0], bl1[1]);
        mma16816(acc[3], ah0, bl1[2], bl1[3]);
        mma16816(acc[4], ah1, bl0[0], bl0[1]);
        mma16816(acc[5], ah1, bl0[2], bl0[3]);
        mma16816(acc[6], ah1, bl1[0], bl1[1]);
        mma16816(acc[7], ah1, bl1[2], bl1[3]);
    }
}

// hi-only GEMM (score nomination)
__device__ __forceinline__ void run_gemm_hi8(u32 aH, u32 bH,
                                             int pitchA, int pitchB,
                                             int lane, int wrow, int cbase, float (*acc)[4])
{
    const u32 aoff0 = (u32)(wrow + (lane & 15)) * pitchA + (u32)(lane >> 4) * 16;
    const u32 aoff1 = aoff0 + 16u * pitchA;
    const u32 boff = (u32)(cbase + (lane & 7) + ((lane >> 4) << 3)) * pitchB
                   + (u32)((lane >> 3) & 1) * 16;
#pragma unroll
    for (int ks = 0; ks < 8; ks++) {
        u32 ah0[4], ah1[4], bh0[4], bh1[4];
        LDSM4(ah0, aH + aoff0 + ks * 32);
        LDSM4(ah1, aH + aoff1 + ks * 32);
        LDSM4(bh0, bH + boff + ks * 32);
        LDSM4(bh1, bH + boff + 16u * pitchB + ks * 32);
        mma16816(acc[0], ah0, bh0[0], bh0[1]);
        mma16816(acc[1], ah0, bh0[2], bh0[3]);
        mma16816(acc[2], ah0, bh1[0], bh1[1]);
        mma16816(acc[3], ah0, bh1[2], bh1[3]);
        mma16816(acc[4], ah1, bh0[0], bh0[1]);
        mma16816(acc[5], ah1, bh0[2], bh0[3]);
        mma16816(acc[6], ah1, bh1[0], bh1[1]);
        mma16816(acc[7], ah1, bh1[2], bh1[3]);
    }
}

// top-3 insert
__device__ __forceinline__ void ins3(float d, int c, float* t, int* ti) {
    if (d < t[0])      { t[2]=t[1]; ti[2]=ti[1]; t[1]=t[0]; ti[1]=ti[0]; t[0]=d; ti[0]=c; }
    else if (d < t[1]) { t[2]=t[1]; ti[2]=ti[1]; t[1]=d; ti[1]=c; }
    else if (d < t[2]) { t[2]=d; ti[2]=c; }
}

__global__ __launch_bounds__(NTHREADS, 1)
void fused_kernel(const float* __restrict__ in,
                  const float* __restrict__ b1, const float* __restrict__ bh,
                  const float* __restrict__ emb,
                  float* __restrict__ out)
{
    extern __shared__ __align__(16) unsigned char smem[];
    const u32 sb = smem_u32(smem);
    char* sc = (char*)smem;

    const int tid    = threadIdx.x;
    const int wid    = tid >> 5;
    const int lane   = tid & 31;
    const int g      = lane >> 2;
    const int q      = lane & 3;
    const int wrow   = (wid & 3) * 32;
    const int cquart = wid >> 2;
    const int cbase  = cquart * 32;
    const int rowBase = blockIdx.x * TM;

    float* sB1 = (float*)(sc + OFF_B1);
    float* sBH = (float*)(sc + OFF_BH);
    float* sVV = (float*)(sc + OFF_VV);
    float* sEE = (float*)(sc + OFF_EE);
    float* sCD = (float*)(sc + OFF_CD);
    int*   sCI = (int*)  (sc + OFF_CI);

    const char* gimg = (const char*)g_img;

    // ---------------- Stage 0: prefetch W1, Wh; split input ----------------
    for (int i = tid; i < 2304; i += NTHREADS)
        cpa16(sb + REG_A + 36864 + i * 16, gimg + IMG_W1 * 2 + i * 16);
    CP_COMMIT();
    for (int i = tid; i < 4352; i += NTHREADS)
        cpa16(sb + REG_D + i * 16, gimg + IMG_WH * 2 + i * 16);
    CP_COMMIT();

    for (int p = tid; p < 128 * 32; p += NTHREADS) {
        int row = p >> 5, pc = p & 31;
        float2 v = *(const float2*)(in + (size_t)(rowBase + row) * S_DIM + 2 * pc);
        __half h0 = __float2half_rn(v.x);
        __half h1 = __float2half_rn(v.y);
        u32 o = (u32)row * 144 + (u32)pc * 4;
        *(u32*)(sc + REG_A + o)         = pkh(__half2float(h0), __half2float(h1));
        *(u32*)(sc + REG_A + 18432 + o) = pkh(v.x - __half2float(h0), v.y - __half2float(h1));
    }
    if (tid < 128) { sB1[tid] = b1[tid]; sBH[tid] = bh[tid]; }
    if (tid < 512) sEE[tid] = g_ee[tid];
    CP_WAIT(1);
    __syncthreads();

    float acc[8][4];

    // ---------------- Stage 1: x1 = relu(in @ W1 + b1) ----------------
#pragma unroll
    for (int t = 0; t < 8; t++)
#pragma unroll
        for (int j = 0; j < 4; j++) acc[t][j] = 0.0f;
    run_gemm<4>(sb + REG_A, sb + REG_A + 18432,
                sb + REG_A + 36864, sb + REG_A + 55296, 144, 144, lane, wrow, cbase, acc);
#pragma unroll
    for (int m = 0; m < 2; m++) {
        int r1 = wrow + m * 16 + g, r2 = r1 + 8;
#pragma unroll
        for (int bt = 0; bt < 2; bt++)
#pragma unroll
            for (int n = 0; n < 2; n++) {
                int c = cbase + bt * 16 + n * 8 + 2 * q;
                float* a = acc[m * 4 + bt * 2 + n];
                float z0 = fmaxf(a[0] + sB1[c],     0.0f);
                float z1 = fmaxf(a[1] + sB1[c + 1], 0.0f);
                float z2 = fmaxf(a[2] + sB1[c],     0.0f);
                float z3 = fmaxf(a[3] + sB1[c + 1], 0.0f);
                __half h0 = __float2half_rn(z0), h1 = __float2half_rn(z1);
                __half h2 = __float2half_rn(z2), h3 = __float2half_rn(z3);
                u32 o1 = (u32)r1 * 272 + (u32)c * 2;
                u32 o2 = (u32)r2 * 272 + (u32)c * 2;
                *(u32*)(sc + REG_C + o1)         = pkh(__half2float(h0), __half2float(h1));
                *(u32*)(sc + REG_C + o2)         = pkh(__half2float(h2), __half2float(h3));
                *(u32*)(sc + REG_C + 34816 + o1) = pkh(z0 - __half2float(h0), z1 - __half2float(h1));
                *(u32*)(sc + REG_C + 34816 + o2) = pkh(z2 - __half2float(h2), z3 - __half2float(h3));
            }
    }
    CP_WAIT(0);
    __syncthreads();

    // ---------------- Stage 2: x2 = relu(x1 @ Wh + bh) ----------------
#pragma unroll
    for (int t = 0; t < 8; t++)
#pragma unroll
        for (int j = 0; j < 4; j++) acc[t][j] = 0.0f;
    run_gemm<8>(sb + REG_C, sb + REG_C + 34816,
                sb + REG_D, sb + REG_D + 34816, 272, 272, lane, wrow, cbase, acc);
    __syncthreads();   // MMA reads of REG_C/REG_D complete

    // prefetch ALL 4 E hi tiles: tiles 0,1 -> REG_C; 2,3 -> REG_D
#pragma unroll
    for (int t4 = 0; t4 < 4; t4++) {
        u32 dst = ((t4 < 2) ? (sb + REG_C) : (sb + REG_D)) + (u32)(t4 & 1) * 34816;
        const char* src = gimg + (IMG_E + t4 * 17408) * 2;
        for (int i = tid; i < 2176; i += NTHREADS)
            cpa16(dst + i * 16, src + i * 16);
        CP_COMMIT();
    }

    // stage 2 epilogue (overlaps fills)
    {
        float vp[2][2] = {{0.0f, 0.0f}, {0.0f, 0.0f}};
#pragma unroll
        for (int m = 0; m < 2; m++) {
            int r1 = wrow + m * 16 + g, r2 = r1 + 8;
#pragma unroll
            for (int bt = 0; bt < 2; bt++)
#pragma unroll
                for (int n = 0; n < 2; n++) {
                    int c = cbase + bt * 16 + n * 8 + 2 * q;
                    float* a = acc[m * 4 + bt * 2 + n];
                    float z0 = fmaxf(a[0] + sBH[c],     0.0f);
                    float z1 = fmaxf(a[1] + sBH[c + 1], 0.0f);
                    float z2 = fmaxf(a[2] + sBH[c],     0.0f);
                    float z3 = fmaxf(a[3] + sBH[c + 1], 0.0f);
                    __half h0 = __float2half_rn(z0), h1 = __float2half_rn(z1);
                    __half h2 = __float2half_rn(z2), h3 = __float2half_rn(z3);
                    float fl0 = z0 - __half2float(h0), fl1 = z1 - __half2float(h1);
                    float fl2 = z2 - __half2float(h2), fl3 = z3 - __half2float(h3);
                    float x0 = __half2float(h0) + __half2float(__float2half_rn(fl0));
                    float x1 = __half2float(h1) + __half2float(__float2half_rn(fl1));
                    float x2 = __half2float(h2) + __half2float(__float2half_rn(fl2));
                    float x3 = __half2float(h3) + __half2float(__float2half_rn(fl3));
                    vp[m][0] = fmaf(x0, x0, vp[m][0]); vp[m][0] = fmaf(x1, x1, vp[m][0]);
                    vp[m][1] = fmaf(x2, x2, vp[m][1]); vp[m][1] = fmaf(x3, x3, vp[m][1]);
                    u32 o1 = (u32)r1 * 272 + (u32)c * 2;
                    u32 o2 = (u32)r2 * 272 + (u32)c * 2;
                    *(u32*)(sc + REG_A + o1)         = pkh(__half2float(h0), __half2float(h1));
                    *(u32*)(sc + REG_A + o2)         = pkh(__half2float(h2), __half2float(h3));
                    *(u32*)(sc + REG_A + 34816 + o1) = pkh(fl0, fl1);
                    *(u32*)(sc + REG_A + 34816 + o2) = pkh(fl2, fl3);
                }
        }
#pragma unroll
        for (int m = 0; m < 2; m++)
#pragma unroll
            for (int h = 0; h < 2; h++) {
                float v = vp[m][h];
                v += __shfl_xor_sync(0xFFFFFFFFu, v, 1);
                v += __shfl_xor_sync(0xFFFFFFFFu, v, 2);
                if (q == 0) sVV[(wrow + m * 16 + g + 8 * h) * 4 + cquart] = v;
            }
    }
    __syncthreads();

    // ---------------- Score: 4 tiles, hi-only, top-3 per quarter ----------
    float vvr[2][2];
#pragma unroll
    for (int m = 0; m < 2; m++)
#pragma unroll
        for (int h = 0; h < 2; h++) {
            int r = wrow + m * 16 + g + 8 * h;
            vvr[m][h] = (sVV[r * 4] + sVV[r * 4 + 1]) + (sVV[r * 4 + 2] + sVV[r * 4 + 3]);
        }
    float td[4][3]; int ti[4][3];
#pragma unroll
    for (int s = 0; s < 4; s++)
#pragma unroll
        for (int k = 0; k < 3; k++) { td[s][k] = __int_as_float(0x7f800000); ti[s][k] = 0; }

#define SCORE_TILE(T)                                                            \
    do {                                                                         \
        u32 buf = (((T) < 2) ? (sb + REG_C) : (sb + REG_D)) + (u32)((T) & 1) * 34816; \
        _Pragma("unroll")                                                        \
        for (int t = 0; t < 8; t++)                                              \
            _Pragma("unroll")                                                    \
            for (int j = 0; j < 4; j++) acc[t][j] = 0.0f;                        \
        run_gemm_hi8(sb + REG_A, buf, 272, 272, lane, wrow, cbase, acc);         \
        int codeBase = (T) * 128 + cbase;                                        \
        _Pragma("unroll")                                                        \
        for (int m = 0; m < 2; m++)                                              \
            _Pragma("unroll")                                                    \
            for (int bt = 0; bt < 2; bt++)                                       \
                _Pragma("unroll")                                                \
                for (int n = 0; n < 2; n++) {                                    \
                    int c = codeBase + bt * 16 + n * 8 + 2 * q;                  \
                    float* a = acc[m * 4 + bt * 2 + n];                          \
                    _Pragma("unroll")                                            \
                    for (int jj = 0; jj < 2; jj++) {                             \
                        int code = c + jj;                                       \
                        float ee = sEE[code];                                    \
                        ins3(fmaf(-2.0f, a[jj],     vvr[m][0]) + ee, code, td[m*2],     ti[m*2]);     \
                        ins3(fmaf(-2.0f, a[2 + jj], vvr[m][1]) + ee, code, td[m*2 + 1], ti[m*2 + 1]); \
                    }                                                            \
                }                                                                \
    } while (0)

    CP_WAIT(3); __syncthreads(); SCORE_TILE(0);
    CP_WAIT(2); __syncthreads(); SCORE_TILE(1);
    CP_WAIT(1); __syncthreads(); SCORE_TILE(2);
    CP_WAIT(0); __syncthreads(); SCORE_TILE(3);

    // ---------------- merge top-3 across q lanes ----------------
#pragma unroll
    for (int s = 0; s < 4; s++) {
#pragma unroll
        for (int mk = 1; mk <= 2; mk <<= 1) {
#pragma unroll
            for (int k = 0; k < 3; k++) {
                float od = __shfl_xor_sync(0xFFFFFFFFu, td[s][k], mk);
                int  oi = __shfl_xor_sync(0xFFFFFFFFu, ti[s][k], mk);
                ins3(od, oi, td[s], ti[s]);
            }
        }
    }
    if (q == 0) {
#pragma unroll
        for (int s = 0; s < 4; s++) {
            int r = wrow + (s >> 1) * 16 + g + 8 * (s & 1);
#pragma unroll
            for (int k = 0; k < 3; k++) {
                sCD[r * 12 + cquart * 3 + k] = td[s][k];
                sCI[r * 12 + cquart * 3 + k] = ti[s][k];
            }
        }
    }
    __syncthreads();

    // ---------------- candidates + exact fp32 re-check + output ----------------
    if (tid < TM) {
        int row = tid;
        float cd[12]; int ci[12];
#pragma unroll
        for (int j = 0; j < 12; j++) { cd[j] = sCD[row * 12 + j]; ci[j] = sCI[row * 12 + j]; }
        float mn = cd[0];
#pragma unroll
        for (int j = 1; j < 12; j++) mn = fminf(mn, cd[j]);
        int cnt = 0; int cidx[12];
#pragma unroll
        for (int j = 0; j < 12; j++)
            if (cd[j] <= mn + MARGIN) cidx[cnt++] = ci[j];

        int bestI;
        if (cnt == 1) {
            bestI = cidx[0];
        } else {
            float dots[12];
#pragma unroll
            for (int j = 0; j < 12; j++) dots[j] = 0.0f;
            float vx = 0.0f;
            for (int i = 0; i < 64; i++) {
                int w = (row + i) & 63;
                u32 hw = *(const u32*)(sc + REG_A + (u32)row * 272 + (u32)w * 4);
                u32 lw = *(const u32*)(sc + REG_A + 34816 + (u32)row * 272 + (u32)w * 4);
                __half2 hh = *reinterpret_cast<__half2*>(&hw);
                __half2 ll = *reinterpret_cast<__half2*>(&lw);
                float x0 = __half2float(hh.x) + __half2float(ll.x);
                float x1 = __half2float(hh.y) + __half2float(ll.y);
                vx = fmaf(x0, x0, vx);
                vx = fmaf(x1, x1, vx);
                for (int j = 0; j < cnt; j++) {
                    const float* ep = emb + (size_t)cidx[j] * H_DIM + 2 * w;
                    dots[j] = fmaf(x0, __ldg(ep),     dots[j]);
                    dots[j] = fmaf(x1, __ldg(ep + 1), dots[j]);
                }
            }
            float bestD = __int_as_float(0x7f800000);
            bestI = 0x7fffffff;
            for (int j = 0; j < cnt; j++) {
                float dd = __fadd_rn(__fsub_rn(vx, __fmul_rn(2.0f, dots[j])), sEE[cidx[j]]);
                bool dup = false;
                for (int kk = 0; kk < j; kk++) dup |= (cidx[kk] == cidx[j]);
                if (!dup && (dd < bestD || (dd == bestD && cidx[j] < bestI))) { bestD = dd; bestI = cidx[j]; }
            }
        }

        int gr = rowBase + row;
        float4 p0 = *(const float4*)(g_probs + bestI * A_DIM);
        float4 p1 = *(const float4*)(g_probs + bestI * A_DIM + 4);
        float4* po = (float4*)out;
        po[gr * 2 + 0] = p0;
        po[gr * 2 + 1] = p1;
        out[(size_t)N_ROWS * A_DIM + gr] = g_value[bestI];
    }
}

// ===================== launch =====================
extern "C" void kernel_launch(void* const* d_in, const int* in_sizes, int n_in,
                              void* d_out, int out_size)
{
    const float* inputs = (const float*)d_in[0];
    const float* W1  = (const float*)d_in[1];
    const float* b1  = (const float*)d_in[2];
    const float* Wh  = (const float*)d_in[3];
    const float* bh  = (const float*)d_in[4];
    const float* emb = (const float*)d_in[5];
    const float* Wa  = (const float*)d_in[6];
    const float* ba  = (const float*)d_in[7];
    const float* Wv  = (const float*)d_in[8];
    const float* bv  = (const float*)d_in[9];

    cudaFuncSetAttribute(fused_kernel,
                         cudaFuncAttributeMaxDynamicSharedMemorySize, SMEM_BYTES);

    prep_all<<<416, 256>>>(emb, Wa, ba, Wv, bv, W1, Wh);
    fused_kernel<<<N_ROWS / TM, NTHREADS, SMEM_BYTES>>>(
        inputs, b1, bh, emb, (float*)d_out);
}

// round 9
// speedup vs baseline: 1.3976x; 1.3976x over previous
#include <cuda_runtime.h>
#include <cuda_fp16.h>
#include <math.h>
#include <stdint.h>

#define N_ROWS  131072
#define S_DIM   64
#define H_DIM   128
#define K_CODES 512
#define A_DIM   8
#define TM      128
#define NTHREADS 512

typedef uint32_t u32;

// ===================== warp-level tensor ops (base PTX) =====================
#define LDSM4(r, addr)                                                        \
    asm volatile("ldmatrix.sync.aligned.m8n8.x4.shared.b16 {%0,%1,%2,%3}, [%4];" \
                 : "=r"((r)[0]), "=r"((r)[1]), "=r"((r)[2]), "=r"((r)[3])     \
                 : "r"(addr))

__device__ __forceinline__ void mma16816(float* c, const u32* a, u32 b0, u32 b1) {
    asm volatile("mma.sync.aligned.m16n8k16.row.col.f32.f16.f16.f32 "
                 "{%0,%1,%2,%3}, {%4,%5,%6,%7}, {%8,%9}, {%0,%1,%2,%3};"
                 : "+f"(c[0]), "+f"(c[1]), "+f"(c[2]), "+f"(c[3])
                 : "r"(a[0]), "r"(a[1]), "r"(a[2]), "r"(a[3]), "r"(b0), "r"(b1));
}

__device__ __forceinline__ u32 smem_u32(const void* p) {
    u32 a; asm("{ .reg .u64 t; cvta.to.shared.u64 t, %1; cvt.u32.u64 %0, t; }"
               : "=r"(a) : "l"(p)); return a;
}
__device__ __forceinline__ u32 pkh(float a, float b) {
    __half2 t; t.x = __float2half_rn(a); t.y = __float2half_rn(b);
    return *reinterpret_cast<u32*>(&t);
}
__device__ __forceinline__ void cpa16(u32 dst, const void* src) {
    asm volatile("cp.async.cg.shared.global [%0], [%1], 16;"
                 :: "r"(dst), "l"(src) : "memory");
}
#define CP_COMMIT() asm volatile("cp.async.commit_group;" ::: "memory")
#define CP_WAIT(n)  asm volatile("cp.async.wait_group %0;" :: "n"(n) : "memory")

// branchless top-3 insert of packed key (dist<<9 | code), ascending
__device__ __forceinline__ void key3(u32 k, u32* t) {
    u32 a = umin(t[0], k);
    u32 b = umax(t[0], k);
    t[0] = a;
    u32 c = umin(t[1], b);
    u32 d = umax(t[1], b);
    t[1] = c;
    t[2] = umin(t[2], d);
}

// ===================== device globals =====================
__device__ float g_ee[K_CODES];
__device__ float g_probs[K_CODES * A_DIM];
__device__ float g_value[K_CODES];

// fp16 images:  W1T hi/lo (pitch 72), WhT hi/lo (pitch 136), E hi-only (4 x [128][136])
#define IMG_W1 0
#define IMG_WH 18432
#define IMG_E  53248
__device__ __half g_img[122880];

// ===================== kernel 1: merged prelim =====================
__global__ void prep_all(const float* __restrict__ emb,
                         const float* __restrict__ Wa, const float* __restrict__ ba,
                         const float* __restrict__ Wv, const float* __restrict__ bv,
                         const float* __restrict__ W1, const float* __restrict__ Wh)
{
    if (blockIdx.x < 64) {
        int code = blockIdx.x * 8 + (threadIdx.x >> 5);
        int lane = threadIdx.x & 31;
        const float* e = emb + code * H_DIM;
        double ee = 0.0;
        float logit[A_DIM];
#pragma unroll
        for (int a = 0; a < A_DIM; a++) logit[a] = 0.0f;
        float val = 0.0f;
#pragma unroll
        for (int j = 0; j < 4; j++) {
            int d = lane + 32 * j;
            float ej = e[d];
            ee += (double)ej * (double)ej;
#pragma unroll
            for (int a = 0; a < A_DIM; a++) logit[a] = fmaf(ej, Wa[d * A_DIM + a], logit[a]);
            val = fmaf(ej, Wv[d], val);
        }
#pragma unroll
        for (int off = 16; off; off >>= 1) {
            ee  += __shfl_xor_sync(0xFFFFFFFFu, ee,  off);
            val += __shfl_xor_sync(0xFFFFFFFFu, val, off);
#pragma unroll
            for (int a = 0; a < A_DIM; a++)
                logit[a] += __shfl_xor_sync(0xFFFFFFFFu, logit[a], off);
        }
        if (lane == 0) {
#pragma unroll
            for (int a = 0; a < A_DIM; a++) logit[a] += ba[a];
            g_ee[code] = (float)ee;
            g_value[code] = val + bv[0];
            float m = logit[0];
#pragma unroll
            for (int a = 1; a < A_DIM; a++) m = fmaxf(m, logit[a]);
            float p[A_DIM], s = 0.0f;
#pragma unroll
            for (int a = 0; a < A_DIM; a++) { p[a] = expf(logit[a] - m); s += p[a]; }
#pragma unroll
            for (int a = 0; a < A_DIM; a++) g_probs[code * A_DIM + a] = p[a] / s;
        }
        return;
    }
    int idx = (blockIdx.x - 64) * 256 + threadIdx.x;
    if (idx < 8192) {                       // W1T hi/lo
        int n = idx >> 6, s = idx & 63;
        float v = W1[s * H_DIM + n];
        __half h = __float2half_rn(v);
        __half l = __float2half_rn(v - __half2float(h));
        int o = n * 72 + s;
        g_img[IMG_W1 + o] = h;
        g_img[IMG_W1 + 9216 + o] = l;
    } else if (idx < 24576) {               // WhT hi/lo
        int j = idx - 8192;
        int n = j >> 7, k = j & 127;
        float v = Wh[k * H_DIM + n];
        __half h = __float2half_rn(v);
        __half l = __float2half_rn(v - __half2float(h));
        int o = n * 136 + k;
        g_img[IMG_WH + o] = h;
        g_img[IMG_WH + 17408 + o] = l;
    } else if (idx < 90112) {               // E hi only
        int j = idx - 24576;
        int g = j >> 7, d = j & 127;
        int t = g >> 7, c = g & 127;
        g_img[IMG_E + t * 17408 + c * 136 + d] = __float2half_rn(emb[g * H_DIM + d]);
    }
}

// ===================== kernel 2: fused main (R5 structure) =====================
#define OFF_B1   0        // float[128]
#define OFF_BH   512
#define OFF_VV   1024     // float[128][2]
#define OFF_EE   2048     // float[512]
#define OFF_EE64 4096     // float[512]  (g_ee * 64)
#define OFF_KEY  6144     // u32[128][6] = 3072 B
#define REG_A    9216     // input hi|lo(+18432) p144; W1 hi(+36864)|lo(+55296); later x2 hi|lo(+34816) p272
#define REG_C    82944    // x1 hi|lo(+34816) p272; later E hi tiles 0(+0),1(+34816)
#define REG_D    152576   // Wh hi|lo(+34816) p272; later E hi tiles 2(+0),3(+34816)
#define SMEM_BYTES 222208

// 3-pass split GEMM, warp tile 16x64 (R5, proven)
template<int KS>
__device__ __forceinline__ void run_gemm4(u32 aH, u32 aL, u32 bH, u32 bL,
                                          int pitchA, int pitchB,
                                          int lane, int wrow, int cbase, float (*acc)[4])
{
    const u32 aoff = (u32)(wrow + (lane & 15)) * pitchA + (u32)(lane >> 4) * 16;
    const u32 boff = (u32)(cbase + (lane & 7) + ((lane >> 4) << 3)) * pitchB
                   + (u32)((lane >> 3) & 1) * 16;
#pragma unroll
    for (int ks = 0; ks < KS; ks++) {
        u32 ah[4], al[4];
        LDSM4(ah, aH + aoff + ks * 32);
        LDSM4(al, aL + aoff + ks * 32);
#pragma unroll
        for (int bt = 0; bt < 4; bt++) {
            u32 bh[4], bl[4];
            LDSM4(bh, bH + boff + (u32)bt * 16 * pitchB + ks * 32);
            mma16816(acc[2 * bt],     ah, bh[0], bh[1]);
            mma16816(acc[2 * bt + 1], ah, bh[2], bh[3]);
            mma16816(acc[2 * bt],     al, bh[0], bh[1]);
            mma16816(acc[2 * bt + 1], al, bh[2], bh[3]);
            LDSM4(bl, bL + boff + (u32)bt * 16 * pitchB + ks * 32);
            mma16816(acc[2 * bt],     ah, bl[0], bl[1]);
            mma16816(acc[2 * bt + 1], ah, bl[2], bl[3]);
        }
    }
}

// hi-only score GEMM, warp tile 16x64
__device__ __forceinline__ void run_gemm_hi(u32 aH, u32 bH,
                                            int pitchA, int pitchB,
                                            int lane, int wrow, int cbase, float (*acc)[4])
{
    const u32 aoff = (u32)(wrow + (lane & 15)) * pitchA + (u32)(lane >> 4) * 16;
    const u32 boff = (u32)(cbase + (lane & 7) + ((lane >> 4) << 3)) * pitchB
                   + (u32)((lane >> 3) & 1) * 16;
#pragma unroll
    for (int ks = 0; ks < 8; ks++) {
        u32 ah[4];
        LDSM4(ah, aH + aoff + ks * 32);
#pragma unroll
        for (int bt = 0; bt < 4; bt++) {
            u32 bh[4];
            LDSM4(bh, bH + boff + (u32)bt * 16 * pitchB + ks * 32);
            mma16816(acc[2 * bt],     ah, bh[0], bh[1]);
            mma16816(acc[2 * bt + 1], ah, bh[2], bh[3]);
        }
    }
}

__global__ __launch_bounds__(NTHREADS, 1)
void fused_kernel(const float* __restrict__ in,
                  const float* __restrict__ b1, const float* __restrict__ bh,
                  const float* __restrict__ emb,
                  float* __restrict__ out)
{
    extern __shared__ __align__(16) unsigned char smem[];
    const u32 sb = smem_u32(smem);
    char* sc = (char*)smem;

    const int tid   = threadIdx.x;
    const int wid   = tid >> 5;
    const int lane  = tid & 31;
    const int g     = lane >> 2;
    const int q     = lane & 3;
    const int wrow  = (wid & 7) * 16;      // row strip (R5)
    const int chalf = wid >> 3;            // column half (R5)
    const int cbase = chalf * 64;
    const int r1 = wrow + g, r2 = r1 + 8;
    const int rowBase = blockIdx.x * TM;

    float* sB1   = (float*)(sc + OFF_B1);
    float* sBH   = (float*)(sc + OFF_BH);
    float* sVV   = (float*)(sc + OFF_VV);
    float* sEE   = (float*)(sc + OFF_EE);
    float* sEE64 = (float*)(sc + OFF_EE64);
    u32*   sKEY  = (u32*)  (sc + OFF_KEY);

    const char* gimg = (const char*)g_img;

    // ---------------- Stage 0: prefetch W1, Wh; split input ----------------
    for (int i = tid; i < 2304; i += NTHREADS)
        cpa16(sb + REG_A + 36864 + i * 16, gimg + IMG_W1 * 2 + i * 16);
    CP_COMMIT();
    for (int i = tid; i < 4352; i += NTHREADS)
        cpa16(sb + REG_D + i * 16, gimg + IMG_WH * 2 + i * 16);
    CP_COMMIT();

    for (int p = tid; p < 128 * 32; p += NTHREADS) {
        int row = p >> 5, pc = p & 31;
        float2 v = *(const float2*)(in + (size_t)(rowBase + row) * S_DIM + 2 * pc);
        __half h0 = __float2half_rn(v.x);
        __half h1 = __float2half_rn(v.y);
        u32 o = (u32)row * 144 + (u32)pc * 4;
        *(u32*)(sc + REG_A + o)         = pkh(__half2float(h0), __half2float(h1));
        *(u32*)(sc + REG_A + 18432 + o) = pkh(v.x - __half2float(h0), v.y - __half2float(h1));
    }
    if (tid < 128) { sB1[tid] = b1[tid]; sBH[tid] = bh[tid]; }
    if (tid < 512) { float e = g_ee[tid]; sEE[tid] = e; sEE64[tid] = e * 64.0f; }
    CP_WAIT(1);
    __syncthreads();

    float acc[8][4];

    // ---------------- Stage 1: x1 = relu(in @ W1 + b1) ----------------
#pragma unroll
    for (int t = 0; t < 8; t++)
#pragma unroll
        for (int j = 0; j < 4; j++) acc[t][j] = 0.0f;
    run_gemm4<4>(sb + REG_A, sb + REG_A + 18432,
                 sb + REG_A + 36864, sb + REG_A + 55296, 144, 144, lane, wrow, cbase, acc);
#pragma unroll
    for (int t = 0; t < 8; t++) {
        int c = cbase + 8 * t + 2 * q;
        float z0 = fmaxf(acc[t][0] + sB1[c],     0.0f);
        float z1 = fmaxf(acc[t][1] + sB1[c + 1], 0.0f);
        float z2 = fmaxf(acc[t][2] + sB1[c],     0.0f);
        float z3 = fmaxf(acc[t][3] + sB1[c + 1], 0.0f);
        __half h0 = __float2half_rn(z0), h1 = __float2half_rn(z1);
        __half h2 = __float2half_rn(z2), h3 = __float2half_rn(z3);
        u32 o1 = (u32)r1 * 272 + (u32)c * 2;
        u32 o2 = (u32)r2 * 272 + (u32)c * 2;
        *(u32*)(sc + REG_C + o1)         = pkh(__half2float(h0), __half2float(h1));
        *(u32*)(sc + REG_C + o2)         = pkh(__half2float(h2), __half2float(h3));
        *(u32*)(sc + REG_C + 34816 + o1) = pkh(z0 - __half2float(h0), z1 - __half2float(h1));
        *(u32*)(sc + REG_C + 34816 + o2) = pkh(z2 - __half2float(h2), z3 - __half2float(h3));
    }
    CP_WAIT(0);
    __syncthreads();

    // ---------------- Stage 2: x2 = relu(x1 @ Wh + bh) ----------------
#pragma unroll
    for (int t = 0; t < 8; t++)
#pragma unroll
        for (int j = 0; j < 4; j++) acc[t][j] = 0.0f;
    run_gemm4<8>(sb + REG_C, sb + REG_C + 34816,
                 sb + REG_D, sb + REG_D + 34816, 272, 272, lane, wrow, cbase, acc);
    __syncthreads();   // MMA reads of REG_C/REG_D complete

    // prefetch all 4 E hi tiles: 0,1 -> REG_C; 2,3 -> REG_D
#pragma unroll
    for (int t4 = 0; t4 < 4; t4++) {
        u32 dst = ((t4 < 2) ? (sb + REG_C) : (sb + REG_D)) + (u32)(t4 & 1) * 34816;
        const char* src = gimg + (IMG_E + t4 * 17408) * 2;
        for (int i = tid; i < 2176; i += NTHREADS)
            cpa16(dst + i * 16, src + i * 16);
        CP_COMMIT();
    }

    // stage 2 epilogue (overlaps fills): relu+bias, split x2 -> REG_A, vv partials
    {
        float vp1 = 0.0f, vp2 = 0.0f;
#pragma unroll
        for (int t = 0; t < 8; t++) {
            int c = cbase + 8 * t + 2 * q;
            float z0 = fmaxf(acc[t][0] + sBH[c],     0.0f);
            float z1 = fmaxf(acc[t][1] + sBH[c + 1], 0.0f);
            float z2 = fmaxf(acc[t][2] + sBH[c],     0.0f);
            float z3 = fmaxf(acc[t][3] + sBH[c + 1], 0.0f);
            __half h0 = __float2half_rn(z0), h1 = __float2half_rn(z1);
            __half h2 = __float2half_rn(z2), h3 = __float2half_rn(z3);
            float fl0 = z0 - __half2float(h0), fl1 = z1 - __half2float(h1);
            float fl2 = z2 - __half2float(h2), fl3 = z3 - __half2float(h3);
            float x0 = __half2float(h0) + __half2float(__float2half_rn(fl0));
            float x1 = __half2float(h1) + __half2float(__float2half_rn(fl1));
            float x2 = __half2float(h2) + __half2float(__float2half_rn(fl2));
            float x3 = __half2float(h3) + __half2float(__float2half_rn(fl3));
            vp1 = fmaf(x0, x0, vp1); vp1 = fmaf(x1, x1, vp1);
            vp2 = fmaf(x2, x2, vp2); vp2 = fmaf(x3, x3, vp2);
            u32 o1 = (u32)r1 * 272 + (u32)c * 2;
            u32 o2 = (u32)r2 * 272 + (u32)c * 2;
            *(u32*)(sc + REG_A + o1)         = pkh(__half2float(h0), __half2float(h1));
            *(u32*)(sc + REG_A + o2)         = pkh(__half2float(h2), __half2float(h3));
            *(u32*)(sc + REG_A + 34816 + o1) = pkh(fl0, fl1);
            *(u32*)(sc + REG_A + 34816 + o2) = pkh(fl2, fl3);
        }
        vp1 += __shfl_xor_sync(0xFFFFFFFFu, vp1, 1);
        vp1 += __shfl_xor_sync(0xFFFFFFFFu, vp1, 2);
        vp2 += __shfl_xor_sync(0xFFFFFFFFu, vp2, 1);
        vp2 += __shfl_xor_sync(0xFFFFFFFFu, vp2, 2);
        if (q == 0) { sVV[r1 * 2 + chalf] = vp1; sVV[r2 * 2 + chalf] = vp2; }
    }
    __syncthreads();

    // ---------------- Score: 4 tiles, hi-only GEMM, packed-key top-3 ----------
    const float vv64a = (sVV[r1 * 2] + sVV[r1 * 2 + 1]) * 64.0f;
    const float vv64b = (sVV[r2 * 2] + sVV[r2 * 2 + 1]) * 64.0f;
    u32 k1[3] = {0xFFFFFFFFu, 0xFFFFFFFFu, 0xFFFFFFFFu};  // row r1's top-3 keys
    u32 k2[3] = {0xFFFFFFFFu, 0xFFFFFFFFu, 0xFFFFFFFFu};  // row r2's

#pragma unroll
    for (int tile = 0; tile < 4; tile++) {
        if (tile == 0) { CP_WAIT(3); }
        else if (tile == 1) { CP_WAIT(2); }
        else if (tile == 2) { CP_WAIT(1); }
        else { CP_WAIT(0); }
        __syncthreads();
        u32 buf = ((tile < 2) ? (sb + REG_C) : (sb + REG_D)) + (u32)(tile & 1) * 34816;

#pragma unroll
        for (int t = 0; t < 8; t++)
#pragma unroll
            for (int j = 0; j < 4; j++) acc[t][j] = 0.0f;
        run_gemm_hi(sb + REG_A, buf, 272, 272, lane, wrow, cbase, acc);

        int codeBase = tile * 128 + cbase;
#pragma unroll
        for (int t = 0; t < 8; t++) {
            int c = codeBase + 8 * t + 2 * q;
#pragma unroll
            for (int jj = 0; jj < 2; jj++) {
                int code = c + jj;
                float e64 = sEE64[code];
                float d64a = fmaf(-128.0f, acc[t][jj],     vv64a + e64);
                float d64b = fmaf(-128.0f, acc[t][2 + jj], vv64b + e64);
                u32 qa = __float2uint_rn(fminf(d64a, 64000.0f));
                u32 qb = __float2uint_rn(fminf(d64b, 64000.0f));
                key3((qa << 9) | (u32)code, k1);
                key3((qb << 9) | (u32)code, k2);
            }
        }
    }

    // merge top-3 across the 4 q lanes of each row half
#pragma unroll
    for (int mk = 1; mk <= 2; mk <<= 1) {
#pragma unroll
        for (int k = 0; k < 3; k++) {
            u32 o1 = __shfl_xor_sync(0xFFFFFFFFu, k1[k], mk);
            u32 o2 = __shfl_xor_sync(0xFFFFFFFFu, k2[k], mk);
            key3(o1, k1);
            key3(o2, k2);
        }
    }
    if (q == 0) {
#pragma unroll
        for (int k = 0; k < 3; k++) {
            sKEY[r1 * 6 + chalf * 3 + k] = k1[k];
            sKEY[r2 * 6 + chalf * 3 + k] = k2[k];
        }
    }
    __syncthreads();

    // ---------------- per-row candidates + exact fp32 re-check + output ------
    if (tid < TM) {
        int row = tid;
        u32 kk[6];
#pragma unroll
        for (int j = 0; j < 6; j++) kk[j] = sKEY[row * 6 + j];
        u32 kmin = kk[0];
#pragma unroll
        for (int j = 1; j < 6; j++) kmin = umin(kmin, kk[j]);
        u32 thr = (kmin >> 9) + 4;   // +0.0625 distance margin

        int cidx[6]; int cnt = 0;
#pragma unroll
        for (int j = 0; j < 6; j++) {
            if ((kk[j] >> 9) <= thr) {
                int c = (int)(kk[j] & 511u);
                bool dup = false;
                for (int p = 0; p < cnt; p++) dup |= (cidx[p] == c);
                if (!dup) cidx[cnt++] = c;
            }
        }

        int bestI;
        if (cnt == 1) {
            bestI = cidx[0];
        } else {
            float dots[6];
#pragma unroll
            for (int j = 0; j < 6; j++) dots[j] = 0.0f;
            float vx = 0.0f;
            for (int i = 0; i < 64; i++) {
                int w = (row + i) & 63;
                u32 hw = *(const u32*)(sc + REG_A + (u32)row * 272 + (u32)w * 4);
                u32 lw = *(const u32*)(sc + REG_A + 34816 + (u32)row * 272 + (u32)w * 4);
                __half2 hh = *reinterpret_cast<__half2*>(&hw);
                __half2 ll = *reinterpret_cast<__half2*>(&lw);
                float x0 = __half2float(hh.x) + __half2float(ll.x);
                float x1 = __half2float(hh.y) + __half2float(ll.y);
                vx = fmaf(x0, x0, vx);
                vx = fmaf(x1, x1, vx);
                for (int j = 0; j < cnt; j++) {
                    const float* ep = emb + (size_t)cidx[j] * H_DIM + 2 * w;
                    dots[j] = fmaf(x0, __ldg(ep),     dots[j]);
                    dots[j] = fmaf(x1, __ldg(ep + 1), dots[j]);
                }
            }
            float bestD = __int_as_float(0x7f800000);
            bestI = 0x7fffffff;
            for (int j = 0; j < cnt; j++) {
                float dd = __fadd_rn(__fsub_rn(vx, __fmul_rn(2.0f, dots[j])), sEE[cidx[j]]);
                if (dd < bestD || (dd == bestD && cidx[j] < bestI)) { bestD = dd; bestI = cidx[j]; }
            }
        }

        int gr = rowBase + row;
        float4 p0 = *(const float4*)(g_probs + bestI * A_DIM);
        float4 p1 = *(const float4*)(g_probs + bestI * A_DIM + 4);
        float4* po = (float4*)out;
        po[gr * 2 + 0] = p0;
        po[gr * 2 + 1] = p1;
        out[(size_t)N_ROWS * A_DIM + gr] = g_value[bestI];
    }
}

// ===================== launch =====================
extern "C" void kernel_launch(void* const* d_in, const int* in_sizes, int n_in,
                              void* d_out, int out_size)
{
    const float* inputs = (const float*)d_in[0];
    const float* W1  = (const float*)d_in[1];
    const float* b1  = (const float*)d_in[2];
    const float* Wh  = (const float*)d_in[3];
    const float* bh  = (const float*)d_in[4];
    const float* emb = (const float*)d_in[5];
    const float* Wa  = (const float*)d_in[6];
    const float* ba  = (const float*)d_in[7];
    const float* Wv  = (const float*)d_in[8];
    const float* bv  = (const float*)d_in[9];

    cudaFuncSetAttribute(fused_kernel,
                         cudaFuncAttributeMaxDynamicSharedMemorySize, SMEM_BYTES);

    prep_all<<<416, 256>>>(emb, Wa, ba, Wv, bv, W1, Wh);
    fused_kernel<<<N_ROWS / TM, NTHREADS, SMEM_BYTES>>>(
        inputs, b1, bh, emb, (float*)d_out);
}

// round 10
// speedup vs baseline: 1.5523x; 1.1107x over previous
#include <cuda_runtime.h>
#include <cuda_fp16.h>
#include <math.h>
#include <stdint.h>

#define N_ROWS  131072
#define S_DIM   64
#define H_DIM   128
#define K_CODES 512
#define A_DIM   8
#define TM      128
#define NTHREADS 512
#define MARGIN  0.05f

typedef uint32_t u32;

// ===================== warp-level tensor ops (base PTX) =====================
#define LDSM4(r, addr)                                                        \
    asm volatile("ldmatrix.sync.aligned.m8n8.x4.shared.b16 {%0,%1,%2,%3}, [%4];" \
                 : "=r"((r)[0]), "=r"((r)[1]), "=r"((r)[2]), "=r"((r)[3])     \
                 : "r"(addr))

__device__ __forceinline__ void mma16816(float* c, const u32* a, u32 b0, u32 b1) {
    asm volatile("mma.sync.aligned.m16n8k16.row.col.f32.f16.f16.f32 "
                 "{%0,%1,%2,%3}, {%4,%5,%6,%7}, {%8,%9}, {%0,%1,%2,%3};"
                 : "+f"(c[0]), "+f"(c[1]), "+f"(c[2]), "+f"(c[3])
                 : "r"(a[0]), "r"(a[1]), "r"(a[2]), "r"(a[3]), "r"(b0), "r"(b1));
}

__device__ __forceinline__ u32 smem_u32(const void* p) {
    u32 a; asm("{ .reg .u64 t; cvta.to.shared.u64 t, %1; cvt.u32.u64 %0, t; }"
               : "=r"(a) : "l"(p)); return a;
}
__device__ __forceinline__ u32 pkh(float a, float b) {
    __half2 t; t.x = __float2half_rn(a); t.y = __float2half_rn(b);
    return *reinterpret_cast<u32*>(&t);
}
__device__ __forceinline__ void cpa16(u32 dst, const void* src) {
    asm volatile("cp.async.cg.shared.global [%0], [%1], 16;"
                 :: "r"(dst), "l"(src) : "memory");
}
#define CP_COMMIT() asm volatile("cp.async.commit_group;" ::: "memory")
#define CP_WAIT(n)  asm volatile("cp.async.wait_group %0;" :: "n"(n) : "memory")

// branchless top-3 insert of packed key (float-bits<<0 masked | code), ascending
__device__ __forceinline__ void key3(u32 k, u32* t) {
    u32 a = umin(t[0], k);
    u32 b = umax(t[0], k);
    t[0] = a;
    u32 c = umin(t[1], b);
    u32 d = umax(t[1], b);
    t[1] = c;
    t[2] = umin(t[2], d);
}

// ===================== device globals =====================
__device__ float g_ee[K_CODES];
__device__ float g_probs[K_CODES * A_DIM];
__device__ float g_value[K_CODES];

// fp16 images:  W1T hi/lo (pitch 72), WhT hi/lo (pitch 136), E hi-only (4 x [128][136])
#define IMG_W1 0
#define IMG_WH 18432
#define IMG_E  53248
__device__ __half g_img[122880];

// ===================== kernel 1: merged prelim =====================
__global__ void prep_all(const float* __restrict__ emb,
                         const float* __restrict__ Wa, const float* __restrict__ ba,
                         const float* __restrict__ Wv, const float* __restrict__ bv,
                         const float* __restrict__ W1, const float* __restrict__ Wh)
{
    if (blockIdx.x < 64) {
        int code = blockIdx.x * 8 + (threadIdx.x >> 5);
        int lane = threadIdx.x & 31;
        const float* e = emb + code * H_DIM;
        double ee = 0.0;
        float logit[A_DIM];
#pragma unroll
        for (int a = 0; a < A_DIM; a++) logit[a] = 0.0f;
        float val = 0.0f;
#pragma unroll
        for (int j = 0; j < 4; j++) {
            int d = lane + 32 * j;
            float ej = e[d];
            ee += (double)ej * (double)ej;
#pragma unroll
            for (int a = 0; a < A_DIM; a++) logit[a] = fmaf(ej, Wa[d * A_DIM + a], logit[a]);
            val = fmaf(ej, Wv[d], val);
        }
#pragma unroll
        for (int off = 16; off; off >>= 1) {
            ee  += __shfl_xor_sync(0xFFFFFFFFu, ee,  off);
            val += __shfl_xor_sync(0xFFFFFFFFu, val, off);
#pragma unroll
            for (int a = 0; a < A_DIM; a++)
                logit[a] += __shfl_xor_sync(0xFFFFFFFFu, logit[a], off);
        }
        if (lane == 0) {
#pragma unroll
            for (int a = 0; a < A_DIM; a++) logit[a] += ba[a];
            g_ee[code] = (float)ee;
            g_value[code] = val + bv[0];
            float m = logit[0];
#pragma unroll
            for (int a = 1; a < A_DIM; a++) m = fmaxf(m, logit[a]);
            float p[A_DIM], s = 0.0f;
#pragma unroll
            for (int a = 0; a < A_DIM; a++) { p[a] = expf(logit[a] - m); s += p[a]; }
#pragma unroll
            for (int a = 0; a < A_DIM; a++) g_probs[code * A_DIM + a] = p[a] / s;
        }
        return;
    }
    int idx = (blockIdx.x - 64) * 256 + threadIdx.x;
    if (idx < 8192) {                       // W1T hi/lo
        int n = idx >> 6, s = idx & 63;
        float v = W1[s * H_DIM + n];
        __half h = __float2half_rn(v);
        __half l = __float2half_rn(v - __half2float(h));
        int o = n * 72 + s;
        g_img[IMG_W1 + o] = h;
        g_img[IMG_W1 + 9216 + o] = l;
    } else if (idx < 24576) {               // WhT hi/lo
        int j = idx - 8192;
        int n = j >> 7, k = j & 127;
        float v = Wh[k * H_DIM + n];
        __half h = __float2half_rn(v);
        __half l = __float2half_rn(v - __half2float(h));
        int o = n * 136 + k;
        g_img[IMG_WH + o] = h;
        g_img[IMG_WH + 17408 + o] = l;
    } else if (idx < 90112) {               // E hi only
        int j = idx - 24576;
        int g = j >> 7, d = j & 127;
        int t = g >> 7, c = g & 127;
        g_img[IMG_E + t * 17408 + c * 136 + d] = __float2half_rn(emb[g * H_DIM + d]);
    }
}

// ===================== kernel 2: fused main =====================
#define OFF_B1   0        // float[128]
#define OFF_BH   512
#define OFF_VV   1024     // float[128][2]
#define OFF_EE   2048     // float[512]
#define OFF_KEY  4096     // u32[128][6] = 3072 B
#define REG_A    7168     // input hi|lo(+18432) p144; W1 hi(+36864)|lo(+55296); later x2 hi|lo(+34816) p272
#define REG_C    80896    // x1 hi|lo(+34816) p272; later E hi tiles 0(+0),1(+34816)
#define REG_D    150528   // Wh hi|lo(+34816) p272; later E hi tiles 2(+0),3(+34816)
#define SMEM_BYTES 220160

// 3-pass split GEMM, warp tile 16x64 (R5, proven)
template<int KS>
__device__ __forceinline__ void run_gemm4(u32 aH, u32 aL, u32 bH, u32 bL,
                                          int pitchA, int pitchB,
                                          int lane, int wrow, int cbase, float (*acc)[4])
{
    const u32 aoff = (u32)(wrow + (lane & 15)) * pitchA + (u32)(lane >> 4) * 16;
    const u32 boff = (u32)(cbase + (lane & 7) + ((lane >> 4) << 3)) * pitchB
                   + (u32)((lane >> 3) & 1) * 16;
#pragma unroll
    for (int ks = 0; ks < KS; ks++) {
        u32 ah[4], al[4];
        LDSM4(ah, aH + aoff + ks * 32);
        LDSM4(al, aL + aoff + ks * 32);
#pragma unroll
        for (int bt = 0; bt < 4; bt++) {
            u32 bh[4], bl[4];
            LDSM4(bh, bH + boff + (u32)bt * 16 * pitchB + ks * 32);
            mma16816(acc[2 * bt],     ah, bh[0], bh[1]);
            mma16816(acc[2 * bt + 1], ah, bh[2], bh[3]);
            mma16816(acc[2 * bt],     al, bh[0], bh[1]);
            mma16816(acc[2 * bt + 1], al, bh[2], bh[3]);
            LDSM4(bl, bL + boff + (u32)bt * 16 * pitchB + ks * 32);
            mma16816(acc[2 * bt],     ah, bl[0], bl[1]);
            mma16816(acc[2 * bt + 1], ah, bl[2], bl[3]);
        }
    }
}

// hi-only score GEMM, warp tile 16x64
__device__ __forceinline__ void run_gemm_hi(u32 aH, u32 bH,
                                            int pitchA, int pitchB,
                                            int lane, int wrow, int cbase, float (*acc)[4])
{
    const u32 aoff = (u32)(wrow + (lane & 15)) * pitchA + (u32)(lane >> 4) * 16;
    const u32 boff = (u32)(cbase + (lane & 7) + ((lane >> 4) << 3)) * pitchB
                   + (u32)((lane >> 3) & 1) * 16;
#pragma unroll
    for (int ks = 0; ks < 8; ks++) {
        u32 ah[4];
        LDSM4(ah, aH + aoff + ks * 32);
#pragma unroll
        for (int bt = 0; bt < 4; bt++) {
            u32 bh[4];
            LDSM4(bh, bH + boff + (u32)bt * 16 * pitchB + ks * 32);
            mma16816(acc[2 * bt],     ah, bh[0], bh[1]);
            mma16816(acc[2 * bt + 1], ah, bh[2], bh[3]);
        }
    }
}

__global__ __launch_bounds__(NTHREADS, 1)
void fused_kernel(const float* __restrict__ in,
                  const float* __restrict__ b1, const float* __restrict__ bh,
                  const float* __restrict__ emb,
                  float* __restrict__ out)
{
    extern __shared__ __align__(16) unsigned char smem[];
    const u32 sb = smem_u32(smem);
    char* sc = (char*)smem;

    const int tid   = threadIdx.x;
    const int wid   = tid >> 5;
    const int lane  = tid & 31;
    const int g     = lane >> 2;
    const int q     = lane & 3;
    const int wrow  = (wid & 7) * 16;      // row strip
    const int chalf = wid >> 3;            // column half
    const int cbase = chalf * 64;
    const int r1 = wrow + g, r2 = r1 + 8;
    const int rowBase = blockIdx.x * TM;

    float* sB1  = (float*)(sc + OFF_B1);
    float* sBH  = (float*)(sc + OFF_BH);
    float* sVV  = (float*)(sc + OFF_VV);
    float* sEE  = (float*)(sc + OFF_EE);
    u32*   sKEY = (u32*)  (sc + OFF_KEY);

    const char* gimg = (const char*)g_img;

    // ---------------- Stage 0: prefetch W1, Wh; split input ----------------
    for (int i = tid; i < 2304; i += NTHREADS)
        cpa16(sb + REG_A + 36864 + i * 16, gimg + IMG_W1 * 2 + i * 16);
    CP_COMMIT();
    for (int i = tid; i < 4352; i += NTHREADS)
        cpa16(sb + REG_D + i * 16, gimg + IMG_WH * 2 + i * 16);
    CP_COMMIT();

    for (int p = tid; p < 128 * 32; p += NTHREADS) {
        int row = p >> 5, pc = p & 31;
        float2 v = *(const float2*)(in + (size_t)(rowBase + row) * S_DIM + 2 * pc);
        __half h0 = __float2half_rn(v.x);
        __half h1 = __float2half_rn(v.y);
        u32 o = (u32)row * 144 + (u32)pc * 4;
        *(u32*)(sc + REG_A + o)         = pkh(__half2float(h0), __half2float(h1));
        *(u32*)(sc + REG_A + 18432 + o) = pkh(v.x - __half2float(h0), v.y - __half2float(h1));
    }
    if (tid < 128) { sB1[tid] = b1[tid]; sBH[tid] = bh[tid]; }
    if (tid < 512) sEE[tid] = g_ee[tid];
    CP_WAIT(1);
    __syncthreads();

    float acc[8][4];

    // ---------------- Stage 1: x1 = relu(in @ W1 + b1) ----------------
#pragma unroll
    for (int t = 0; t < 8; t++)
#pragma unroll
        for (int j = 0; j < 4; j++) acc[t][j] = 0.0f;
    run_gemm4<4>(sb + REG_A, sb + REG_A + 18432,
                 sb + REG_A + 36864, sb + REG_A + 55296, 144, 144, lane, wrow, cbase, acc);
#pragma unroll
    for (int t = 0; t < 8; t++) {
        int c = cbase + 8 * t + 2 * q;
        float z0 = fmaxf(acc[t][0] + sB1[c],     0.0f);
        float z1 = fmaxf(acc[t][1] + sB1[c + 1], 0.0f);
        float z2 = fmaxf(acc[t][2] + sB1[c],     0.0f);
        float z3 = fmaxf(acc[t][3] + sB1[c + 1], 0.0f);
        __half h0 = __float2half_rn(z0), h1 = __float2half_rn(z1);
        __half h2 = __float2half_rn(z2), h3 = __float2half_rn(z3);
        u32 o1 = (u32)r1 * 272 + (u32)c * 2;
        u32 o2 = (u32)r2 * 272 + (u32)c * 2;
        *(u32*)(sc + REG_C + o1)         = pkh(__half2float(h0), __half2float(h1));
        *(u32*)(sc + REG_C + o2)         = pkh(__half2float(h2), __half2float(h3));
        *(u32*)(sc + REG_C + 34816 + o1) = pkh(z0 - __half2float(h0), z1 - __half2float(h1));
        *(u32*)(sc + REG_C + 34816 + o2) = pkh(z2 - __half2float(h2), z3 - __half2float(h3));
    }
    CP_WAIT(0);
    __syncthreads();

    // ---------------- Stage 2: x2 = relu(x1 @ Wh + bh) ----------------
#pragma unroll
    for (int t = 0; t < 8; t++)
#pragma unroll
        for (int j = 0; j < 4; j++) acc[t][j] = 0.0f;
    run_gemm4<8>(sb + REG_C, sb + REG_C + 34816,
                 sb + REG_D, sb + REG_D + 34816, 272, 272, lane, wrow, cbase, acc);
    __syncthreads();   // MMA reads of REG_C/REG_D complete

    // prefetch all 4 E hi tiles: 0,1 -> REG_C; 2,3 -> REG_D
#pragma unroll
    for (int t4 = 0; t4 < 4; t4++) {
        u32 dst = ((t4 < 2) ? (sb + REG_C) : (sb + REG_D)) + (u32)(t4 & 1) * 34816;
        const char* src = gimg + (IMG_E + t4 * 17408) * 2;
        for (int i = tid; i < 2176; i += NTHREADS)
            cpa16(dst + i * 16, src + i * 16);
    }
    CP_COMMIT();

    // stage 2 epilogue (overlaps fills): relu+bias, split x2 -> REG_A, vv partials
    {
        float vp1 = 0.0f, vp2 = 0.0f;
#pragma unroll
        for (int t = 0; t < 8; t++) {
            int c = cbase + 8 * t + 2 * q;
            float z0 = fmaxf(acc[t][0] + sBH[c],     0.0f);
            float z1 = fmaxf(acc[t][1] + sBH[c + 1], 0.0f);
            float z2 = fmaxf(acc[t][2] + sBH[c],     0.0f);
            float z3 = fmaxf(acc[t][3] + sBH[c + 1], 0.0f);
            __half h0 = __float2half_rn(z0), h1 = __float2half_rn(z1);
            __half h2 = __float2half_rn(z2), h3 = __float2half_rn(z3);
            float fl0 = z0 - __half2float(h0), fl1 = z1 - __half2float(h1);
            float fl2 = z2 - __half2float(h2), fl3 = z3 - __half2float(h3);
            float x0 = __half2float(h0) + __half2float(__float2half_rn(fl0));
            float x1 = __half2float(h1) + __half2float(__float2half_rn(fl1));
            float x2 = __half2float(h2) + __half2float(__float2half_rn(fl2));
            float x3 = __half2float(h3) + __half2float(__float2half_rn(fl3));
            vp1 = fmaf(x0, x0, vp1); vp1 = fmaf(x1, x1, vp1);
            vp2 = fmaf(x2, x2, vp2); vp2 = fmaf(x3, x3, vp2);
            u32 o1 = (u32)r1 * 272 + (u32)c * 2;
            u32 o2 = (u32)r2 * 272 + (u32)c * 2;
            *(u32*)(sc + REG_A + o1)         = pkh(__half2float(h0), __half2float(h1));
            *(u32*)(sc + REG_A + o2)         = pkh(__half2float(h2), __half2float(h3));
            *(u32*)(sc + REG_A + 34816 + o1) = pkh(fl0, fl1);
            *(u32*)(sc + REG_A + 34816 + o2) = pkh(fl2, fl3);
        }
        vp1 += __shfl_xor_sync(0xFFFFFFFFu, vp1, 1);
        vp1 += __shfl_xor_sync(0xFFFFFFFFu, vp1, 2);
        vp2 += __shfl_xor_sync(0xFFFFFFFFu, vp2, 1);
        vp2 += __shfl_xor_sync(0xFFFFFFFFu, vp2, 2);
        if (q == 0) { sVV[r1 * 2 + chalf] = vp1; sVV[r2 * 2 + chalf] = vp2; }
    }
    CP_WAIT(0);
    __syncthreads();   // x2 image + vv + ALL E tiles ready; nothing rewritten below

    // ---------------- Score: 4 tiles, barrier-free, float-bit keys ----------
    const float vva = sVV[r1 * 2] + sVV[r1 * 2 + 1];
    const float vvb = sVV[r2 * 2] + sVV[r2 * 2 + 1];
    u32 k1[3] = {0xFFFFFFFFu, 0xFFFFFFFFu, 0xFFFFFFFFu};
    u32 k2[3] = {0xFFFFFFFFu, 0xFFFFFFFFu, 0xFFFFFFFFu};

#pragma unroll
    for (int tile = 0; tile < 4; tile++) {
        u32 buf = ((tile < 2) ? (sb + REG_C) : (sb + REG_D)) + (u32)(tile & 1) * 34816;

#pragma unroll
        for (int t = 0; t < 8; t++)
#pragma unroll
            for (int j = 0; j < 4; j++) acc[t][j] = 0.0f;
        run_gemm_hi(sb + REG_A, buf, 272, 272, lane, wrow, cbase, acc);

        int codeBase = tile * 128 + cbase;
#pragma unroll
        for (int t = 0; t < 8; t++) {
            int c = codeBase + 8 * t + 2 * q;
#pragma unroll
            for (int jj = 0; jj < 2; jj++) {
                int code = c + jj;
                float ee = sEE[code];
                float da = fmaf(-2.0f, acc[t][jj],     vva) + ee;   // > 0
                float db = fmaf(-2.0f, acc[t][2 + jj], vvb) + ee;
                key3((__float_as_uint(da) & 0xFFFFFE00u) | (u32)code, k1);
                key3((__float_as_uint(db) & 0xFFFFFE00u) | (u32)code, k2);
            }
        }
    }

    // merge top-3 across the 4 q lanes of each row half
#pragma unroll
    for (int mk = 1; mk <= 2; mk <<= 1) {
#pragma unroll
        for (int k = 0; k < 3; k++) {
            u32 o1 = __shfl_xor_sync(0xFFFFFFFFu, k1[k], mk);
            u32 o2 = __shfl_xor_sync(0xFFFFFFFFu, k2[k], mk);
            key3(o1, k1);
            key3(o2, k2);
        }
    }
    if (q == 0) {
#pragma unroll
        for (int k = 0; k < 3; k++) {
            sKEY[r1 * 6 + chalf * 3 + k] = k1[k];
            sKEY[r2 * 6 + chalf * 3 + k] = k2[k];
        }
    }
    __syncthreads();

    // ---------------- per-row candidates + exact fp32 re-check + output ------
    if (tid < TM) {
        int row = tid;
        u32 kk[6];
#pragma unroll
        for (int j = 0; j < 6; j++) kk[j] = sKEY[row * 6 + j];
        u32 kmin = kk[0];
#pragma unroll
        for (int j = 1; j < 6; j++) kmin = umin(kmin, kk[j]);
        float thr = __uint_as_float(kmin & 0xFFFFFE00u) + MARGIN;

        int cidx[6]; int cnt = 0;
#pragma unroll
        for (int j = 0; j < 6; j++) {
            if (__uint_as_float(kk[j] & 0xFFFFFE00u) <= thr) {
                int c = (int)(kk[j] & 511u);
                bool dup = false;
                for (int p = 0; p < cnt; p++) dup |= (cidx[p] == c);
                if (!dup) cidx[cnt++] = c;
            }
        }

        int bestI;
        if (cnt == 1) {
            bestI = cidx[0];
        } else {
            float dots[6];
#pragma unroll
            for (int j = 0; j < 6; j++) dots[j] = 0.0f;
            float vx = 0.0f;
            for (int i = 0; i < 64; i++) {
                int w = (row + i) & 63;
                u32 hw = *(const u32*)(sc + REG_A + (u32)row * 272 + (u32)w * 4);
                u32 lw = *(const u32*)(sc + REG_A + 34816 + (u32)row * 272 + (u32)w * 4);
                __half2 hh = *reinterpret_cast<__half2*>(&hw);
                __half2 ll = *reinterpret_cast<__half2*>(&lw);
                float x0 = __half2float(hh.x) + __half2float(ll.x);
                float x1 = __half2float(hh.y) + __half2float(ll.y);
                vx = fmaf(x0, x0, vx);
                vx = fmaf(x1, x1, vx);
                for (int j = 0; j < cnt; j++) {
                    const float* ep = emb + (size_t)cidx[j] * H_DIM + 2 * w;
                    dots[j] = fmaf(x0, __ldg(ep),     dots[j]);
                    dots[j] = fmaf(x1, __ldg(ep + 1), dots[j]);
                }
            }
            float bestD = __int_as_float(0x7f800000);
            bestI = 0x7fffffff;
            for (int j = 0; j < cnt; j++) {
                float dd = __fadd_rn(__fsub_rn(vx, __fmul_rn(2.0f, dots[j])), sEE[cidx[j]]);
                if (dd < bestD || (dd == bestD && cidx[j] < bestI)) { bestD = dd; bestI = cidx[j]; }
            }
        }

        int gr = rowBase + row;
        float4 p0 = *(const float4*)(g_probs + bestI * A_DIM);
        float4 p1 = *(const float4*)(g_probs + bestI * A_DIM + 4);
        float4* po = (float4*)out;
        po[gr * 2 + 0] = p0;
        po[gr * 2 + 1] = p1;
        out[(size_t)N_ROWS * A_DIM + gr] = g_value[bestI];
    }
}

// ===================== launch =====================
extern "C" void kernel_launch(void* const* d_in, const int* in_sizes, int n_in,
                              void* d_out, int out_size)
{
    const float* inputs = (const float*)d_in[0];
    const float* W1  = (const float*)d_in[1];
    const float* b1  = (const float*)d_in[2];
    const float* Wh  = (const float*)d_in[3];
    const float* bh  = (const float*)d_in[4];
    const float* emb = (const float*)d_in[5];
    const float* Wa  = (const float*)d_in[6];
    const float* ba  = (const float*)d_in[7];
    const float* Wv  = (const float*)d_in[8];
    const float* bv  = (const float*)d_in[9];

    cudaFuncSetAttribute(fused_kernel,
                         cudaFuncAttributeMaxDynamicSharedMemorySize, SMEM_BYTES);

    prep_all<<<416, 256>>>(emb, Wa, ba, Wv, bv, W1, Wh);
    fused_kernel<<<N_ROWS / TM, NTHREADS, SMEM_BYTES>>>(
        inputs, b1, bh, emb, (float*)d_out);
}